// round 3
// baseline (speedup 1.0000x reference)
#include <cuda_runtime.h>
#include <math.h>

#define HH 512
#define WW 512
#define NB 32
#define NPIX (HH*WW)
#define EPSV 1e-8f
#define INV_A (1.0f/252004.0f)   // 1/(502*502)
#define SKN 528
#define SK(i) ((i) + ((i) >> 5))

// ---------------- static device storage (no runtime alloc allowed) ----------
__device__ float2 g_z1[NB*NPIX];       // 64 MB: pass1 complex output
__device__ float2 g_z2[NB*NPIX];       // 64 MB: transposed complex
__device__ float  g_tzm[NPIX];
__device__ float2 g_tw[512];
__device__ double g_tsum;
__device__ double g_tvar;
__device__ float  g_fmean[NB];
__device__ float  g_band1[NB][11][WW];
__device__ float  g_band2[NB][11][WW];
__device__ float  g_denom[NB][11][11];
__device__ double g_cc[NB][11][11];
__device__ float  g_shx[NB], g_shy[NB];
__device__ float2 g_phx[NB][512];
__device__ float2 g_phy[NB][512];

// ---------------- complex helpers -------------------------------------------
__device__ __forceinline__ float2 cmulf(float2 a, float2 b){
  return make_float2(a.x*b.x - a.y*b.y, a.x*b.y + a.y*b.x);
}
__device__ __forceinline__ float2 caddf(float2 a, float2 b){ return make_float2(a.x+b.x, a.y+b.y); }
__device__ __forceinline__ float2 csubf(float2 a, float2 b){ return make_float2(a.x-b.x, a.y-b.y); }
__device__ __forceinline__ float2 mulnegi(float2 a){ return make_float2(a.y, -a.x); }

__device__ __forceinline__ void dft8(float2 a[8]){
  const float RT = 0.70710678118654752440f;
  float2 s0=caddf(a[0],a[4]), s1=caddf(a[1],a[5]), s2=caddf(a[2],a[6]), s3=caddf(a[3],a[7]);
  float2 d0=csubf(a[0],a[4]), d1=csubf(a[1],a[5]), d2=csubf(a[2],a[6]), d3=csubf(a[3],a[7]);
  d1 = cmulf(d1, make_float2( RT,-RT));
  d2 = mulnegi(d2);
  d3 = cmulf(d3, make_float2(-RT,-RT));
  float2 p0=caddf(s0,s2), p1=caddf(s1,s3), m0=csubf(s0,s2), m1=mulnegi(csubf(s1,s3));
  float2 q0=caddf(d0,d2), q1=caddf(d1,d3), n0=csubf(d0,d2), n1=mulnegi(csubf(d1,d3));
  a[0]=caddf(p0,p1); a[4]=csubf(p0,p1); a[2]=caddf(m0,m1); a[6]=csubf(m0,m1);
  a[1]=caddf(q0,q1); a[5]=csubf(q0,q1); a[3]=caddf(n0,n1); a[7]=csubf(n0,n1);
}

template<int L>
__device__ __forceinline__ void stage_load(const float* re, const float* im,
                                           const float2* tw, float2 a[8], int t){
  #pragma unroll
  for (int r = 0; r < 8; r++){
    int i = t + 64*r;
    a[r] = make_float2(re[SK(i)], im[SK(i)]);
  }
  if (L > 1){
    int jm = t % L;
    #pragma unroll
    for (int r = 1; r < 8; r++){
      float2 w = tw[(jm * r * (64/L)) & 511];
      a[r] = cmulf(a[r], w);
    }
  }
}

template<int L>
__device__ __forceinline__ void stage_store(float* re, float* im, const float2 a[8], int t){
  int jd = t / L, jm = t % L;
  #pragma unroll
  for (int r = 0; r < 8; r++){
    int i = jd*8*L + jm + L*r;
    re[SK(i)] = a[r].x; im[SK(i)] = a[r].y;
  }
}

// Full 512-pt forward FFT on registers a[] (a[r] = x[t+64r] in, a[r] = X[t+64r] out).
// Uses re/im smem (SKN floats each). Caller guarantees smem not otherwise in use.
// Block-wide syncs inside: ALL block threads must call this together.
__device__ __forceinline__ void fft512(float2 a[8], float* re, float* im,
                                       const float2* stw, int t){
  dft8(a);
  stage_store<1>(re, im, a, t);
  __syncthreads();
  stage_load<8>(re, im, stw, a, t);
  dft8(a);
  __syncthreads();              // FIX: stage writes must not race prior reads
  stage_store<8>(re, im, a, t);
  __syncthreads();
  stage_load<64>(re, im, stw, a, t);
  dft8(a);
}

// ---------------- init -------------------------------------------------------
__global__ void k_init(){
  int t = threadIdx.x;
  if (t < 512){
    double ang = -2.0 * 3.14159265358979323846 * (double)t / 512.0;
    g_tw[t] = make_float2((float)cos(ang), (float)sin(ang));
  }
  double* cc = &g_cc[0][0][0];
  for (int i = t; i < NB*121; i += blockDim.x) cc[i] = 0.0;
  if (t == 0){ g_tsum = 0.0; g_tvar = 0.0; }
}

// ---------------- template stats ---------------------------------------------
__global__ void k_tsum(const float* __restrict__ tpl){
  double s = 0.0;
  for (int i = blockIdx.x*blockDim.x + threadIdx.x; i < NPIX; i += gridDim.x*blockDim.x)
    s += (double)tpl[i];
  __shared__ double sd[256];
  sd[threadIdx.x] = s; __syncthreads();
  for (int o = 128; o; o >>= 1){ if (threadIdx.x < o) sd[threadIdx.x] += sd[threadIdx.x+o]; __syncthreads(); }
  if (threadIdx.x == 0) atomicAdd(&g_tsum, sd[0]);
}

__global__ void k_tzm(const float* __restrict__ tpl){
  float mean = (float)(g_tsum / (double)NPIX);
  double s = 0.0;
  for (int i = blockIdx.x*blockDim.x + threadIdx.x; i < NPIX; i += gridDim.x*blockDim.x){
    float z = tpl[i] - mean;
    g_tzm[i] = z;
    s += (double)(z*z);
  }
  __shared__ double sd[256];
  sd[threadIdx.x] = s; __syncthreads();
  for (int o = 128; o; o >>= 1){ if (threadIdx.x < o) sd[threadIdx.x] += sd[threadIdx.x+o]; __syncthreads(); }
  if (threadIdx.x == 0) atomicAdd(&g_tvar, sd[0]);
}

// ---------------- per-frame stats: mean + column band sums --------------------
__global__ void k_frame(const float* __restrict__ fr){
  int b = blockIdx.x;
  int j = threadIdx.x;                 // 512 threads, one per column
  const float* xb = fr + (size_t)b*NPIX;
  float s1 = 0.f, s2 = 0.f;
  #pragma unroll 8
  for (int i = 0; i < HH; i++){
    float v = xb[(size_t)i*WW + j];
    s1 += v; s2 = fmaf(v, v, s2);
  }
  float topv[10], botv[10];
  #pragma unroll
  for (int i = 0; i < 10; i++) topv[i] = xb[(size_t)i*WW + j];
  #pragma unroll
  for (int i = 0; i < 10; i++) botv[i] = xb[(size_t)(502+i)*WW + j];
  float bs1[11], bs2[11];
  bs1[10] = 0.f; bs2[10] = 0.f;
  #pragma unroll
  for (int m = 9; m >= 0; m--){
    bs1[m] = bs1[m+1] + botv[m];
    bs2[m] = bs2[m+1] + botv[m]*botv[m];
  }
  float tp1 = 0.f, tp2 = 0.f;
  #pragma unroll
  for (int p = 0; p < 11; p++){
    g_band1[b][p][j] = s1 - tp1 - bs1[p];
    g_band2[b][p][j] = s2 - tp2 - bs2[p];
    if (p < 10){ tp1 += topv[p]; tp2 += topv[p]*topv[p]; }
  }
  __shared__ float sd[512];
  sd[j] = s1; __syncthreads();
  for (int o = 256; o; o >>= 1){ if (j < o) sd[j] += sd[j+o]; __syncthreads(); }
  if (j == 0) g_fmean[b] = sd[0] / (float)NPIX;
}

// ---------------- denominator: 121 window stddevs per frame ------------------
__global__ void k_denom(){
  int b = blockIdx.x;
  int t = threadIdx.x;
  if (t >= 121) return;
  int p = t / 11, q = t % 11;
  float s1 = 0.f, s2 = 0.f;
  for (int j = q; j < q + 502; j++){
    s1 += g_band1[b][p][j];
    s2 += g_band2[b][p][j];
  }
  float ls  = s1 * INV_A;
  float lsq = s2 * INV_A;
  float var = lsq - ls*ls*INV_A + EPSV;
  if (var < 0.f) var = 0.f;
  float tvar = (float)g_tvar + EPSV;
  g_denom[b][p][q] = sqrtf(tvar * var);
}

// ---------------- direct circular cross-correlation (121 shifts) -------------
#define CC_ROWS 4
__global__ void k_cc(const float* __restrict__ fr){
  __shared__ float sx[CC_ROWS*WW];     // 8 KB
  __shared__ float st[14*522];         // 29.2 KB
  __shared__ float wsum[8*11];
  int b  = blockIdx.y;
  int r0 = blockIdx.x * CC_ROWS;
  int tid = threadIdx.x;               // 256
  float fm = g_fmean[b];
  const float* xb = fr + (size_t)b*NPIX;
  for (int e = tid; e < CC_ROWS*WW; e += 256){
    int i = e >> 9, j = e & 511;
    sx[e] = xb[(size_t)(r0+i)*WW + j] - fm;
  }
  for (int e = tid; e < 14*522; e += 256){
    int rr = e / 522, c = e - rr*522;
    int gi = (r0 - 5 + rr) & 511;
    int gj = (c - 5) & 511;
    st[e] = g_tzm[gi*WW + gj];
  }
  __syncthreads();
  int jg = tid & 63;
  int il = tid >> 6;                   // 0..3
  int j0 = jg * 8;
  int lane = tid & 31, warp = tid >> 5;
  float xv[8];
  {
    const float* xr = sx + il*WW + j0;
    #pragma unroll
    for (int u = 0; u < 8; u++) xv[u] = xr[u];
  }
  for (int dxi = 0; dxi < 11; dxi++){
    float acc[11];
    #pragma unroll
    for (int d = 0; d < 11; d++) acc[d] = 0.f;
    int trow = il - dxi + 10;          // in [0,13]
    const float* trp = st + trow*522 + j0;
    float tv[18];
    #pragma unroll
    for (int u = 0; u < 18; u++) tv[u] = trp[u];
    #pragma unroll
    for (int d = 0; d < 11; d++)
      #pragma unroll
      for (int u = 0; u < 8; u++)
        acc[d] = fmaf(xv[u], tv[u + 10 - d], acc[d]);
    #pragma unroll
    for (int d = 0; d < 11; d++){
      float v = acc[d];
      for (int o = 16; o; o >>= 1) v += __shfl_down_sync(0xffffffffu, v, o);
      if (lane == 0) wsum[warp*11 + d] = v;
    }
    __syncthreads();
    if (tid < 11){
      float s = 0.f;
      #pragma unroll
      for (int w = 0; w < 8; w++) s += wsum[w*11 + tid];
      atomicAdd(&g_cc[b][dxi][tid], (double)s);
    }
    __syncthreads();
  }
}

// ---------------- argmax + log-parabola subpixel shifts -----------------------
__device__ __forceinline__ float nccval(int b, int p, int q){
  float num = (float)fabs(g_cc[b][p][q]);
  float den = g_denom[b][p][q];
  float v = num / den;
  if (isnan(v)) v = 0.f;
  return v;
}

__global__ void k_shift(){
  int b = threadIdx.x;
  if (b >= NB) return;
  float best = -1e30f; int am = 0;
  for (int t = 0; t < 121; t++){
    float v = nccval(b, t/11, t%11);
    if (v > best){ best = v; am = t; }
  }
  int xi = am / 11, yi = am % 11;
  float shx = -(float)(xi - 5);
  float shy = -(float)(yi - 5);
  int xm = xi - 1; if (xm < 0) xm += 11;   // jnp negative index wraps
  int xp = xi + 1; if (xp > 10) xp = 10;   // jnp OOB gather clamps
  int ym = yi - 1; if (ym < 0) ym += 11;
  int yp = yi + 1; if (yp > 10) yp = 10;
  float l0  = logf(nccval(b, xi, yi));
  float lxm = logf(nccval(b, xm, yi));
  float lxp = logf(nccval(b, xp, yi));
  float lym = logf(nccval(b, xi, ym));
  float lyp = logf(nccval(b, xi, yp));
  shx -= (lxm - lxp) / (2.f*lxm - 4.f*l0 + 2.f*lxp);
  shy -= (lym - lyp) / (2.f*lym - 4.f*l0 + 2.f*lyp);
  g_shx[b] = shx; g_shy[b] = shy;
}

// ---------------- phase tables: exp(-2*pi*i*sh*Nr[k]/512) ---------------------
__global__ void k_phase(){   // grid 32, block 512
  int b = blockIdx.x, k = threadIdx.x;
  float nr = (k < 256) ? (float)k : (float)(k - 512);
  float sy = g_shy[b], sx = g_shx[b];
  float2 py, px;
  sincospif(-sy * nr * (1.f/256.f), &py.y, &py.x);
  sincospif(-sx * nr * (1.f/256.f), &px.y, &px.x);
  g_phy[b][k] = py;
  g_phx[b][k] = px;
}

// ---------------- pass 1: rows along j, real in -> complex out ----------------
__global__ void k_pass1(const float* __restrict__ fr){
  __shared__ float sre[4][SKN], sim[4][SKN];
  __shared__ float2 stw[512];
  int tid = threadIdx.x;
  int rl  = tid >> 6;
  int t   = tid & 63;
  int grow = blockIdx.x * 4 + rl;          // b*512 + i
  int b = grow >> 9;
  const float* rin = fr + (size_t)grow * 512;
  float2* rout     = g_z1 + (size_t)grow * 512;
  const float2* ph = &g_phy[b][0];

  for (int i = tid; i < 512; i += 256) stw[i] = g_tw[i];

  float* re = sre[rl]; float* im = sim[rl];
  float2 a[8];
  #pragma unroll
  for (int r = 0; r < 8; r++) a[r] = make_float2(rin[t + 64*r], 0.f);
  __syncthreads();   // stw ready
  fft512(a, re, im, stw, t);
  #pragma unroll
  for (int r = 0; r < 8; r++){
    float2 p = ph[t + 64*r];
    float xr = a[r].x*p.x - a[r].y*p.y;
    float xi = a[r].x*p.y + a[r].y*p.x;
    a[r] = make_float2(xr * (1.f/512.f), -xi * (1.f/512.f));   // conj + scale
  }
  __syncthreads();   // all smem reads done before inverse writes
  fft512(a, re, im, stw, t);
  // result = conj(z1): store z1
  #pragma unroll
  for (int r = 0; r < 8; r++) rout[t + 64*r] = make_float2(a[r].x, -a[r].y);
}

// ---------------- complex 32x32 tiled transpose g_z1 -> g_z2 ------------------
__global__ void k_transpose(){
  __shared__ float2 tile[32][33];
  int b = blockIdx.z;
  const float2* ib = g_z1 + (size_t)b*NPIX;
  float2* ob = g_z2 + (size_t)b*NPIX;
  int x = blockIdx.x*32 + threadIdx.x;
  int y = blockIdx.y*32 + threadIdx.y;
  #pragma unroll
  for (int r = 0; r < 32; r += 8)
    tile[threadIdx.y + r][threadIdx.x] = ib[(size_t)(y + r)*512 + x];
  __syncthreads();
  int x2 = blockIdx.y*32 + threadIdx.x;
  int y2 = blockIdx.x*32 + threadIdx.y;
  #pragma unroll
  for (int r = 0; r < 32; r += 8)
    ob[(size_t)(y2 + r)*512 + x2] = tile[threadIdx.x][threadIdx.y + r];
}

// ---------------- pass 2: rows along i (transposed), complex in -> real out ---
__global__ void k_pass2(float* __restrict__ out){
  __shared__ float sre[4][SKN], sim[4][SKN];
  __shared__ float2 stw[512];
  int tid = threadIdx.x;
  int rl  = tid >> 6;
  int t   = tid & 63;
  int grow = blockIdx.x * 4 + rl;          // b*512 + j
  int b = grow >> 9;
  const float2* rin = g_z2 + (size_t)grow * 512;
  float* rout       = out + (size_t)grow * 512;   // out[b, j*512 + i]
  const float2* ph  = &g_phx[b][0];

  for (int i = tid; i < 512; i += 256) stw[i] = g_tw[i];

  float* re = sre[rl]; float* im = sim[rl];
  float2 a[8];
  #pragma unroll
  for (int r = 0; r < 8; r++) a[r] = rin[t + 64*r];
  __syncthreads();   // stw ready
  fft512(a, re, im, stw, t);
  #pragma unroll
  for (int r = 0; r < 8; r++){
    float2 p = ph[t + 64*r];
    float xr = a[r].x*p.x - a[r].y*p.y;
    float xi = a[r].x*p.y + a[r].y*p.x;
    a[r] = make_float2(xr * (1.f/512.f), -xi * (1.f/512.f));   // conj + scale
  }
  __syncthreads();
  fft512(a, re, im, stw, t);
  // real(z2) = real(conj(z2)) = a.x
  #pragma unroll
  for (int r = 0; r < 8; r++) rout[t + 64*r] = a[r].x;
}

// ---------------- launcher ----------------------------------------------------
extern "C" void kernel_launch(void* const* d_in, const int* in_sizes, int n_in,
                              void* d_out, int out_size){
  const float* fr  = (const float*)d_in[0];
  const float* tpl = (const float*)d_in[1];
  if (n_in >= 2 && in_sizes[0] < in_sizes[1]){   // defensive: order by size
    fr  = (const float*)d_in[1];
    tpl = (const float*)d_in[0];
  }
  float* out = (float*)d_out;
  k_init<<<1, 512>>>();
  k_tsum<<<64, 256>>>(tpl);
  k_tzm<<<64, 256>>>(tpl);
  k_frame<<<32, 512>>>(fr);
  k_denom<<<32, 128>>>();
  k_cc<<<dim3(128, 32), 256>>>(fr);
  k_shift<<<1, 32>>>();
  k_phase<<<32, 512>>>();
  k_pass1<<<4096, 256>>>(fr);
  k_transpose<<<dim3(16, 16, 32), dim3(32, 8)>>>();
  k_pass2<<<4096, 256>>>(out);
}

// round 4
// speedup vs baseline: 1.5716x; 1.5716x over previous
#include <cuda_runtime.h>
#include <math.h>

#define HH 512
#define WW 512
#define NB 32
#define NPIX (HH*WW)
#define EPSV 1e-8f
#define INV_A (1.0f/252004.0f)   // 1/(502*502)
#define SKN 528
#define SK(i) ((i) + ((i) >> 5))

// ---------------- static device storage (no runtime alloc allowed) ----------
__device__ float2 g_z2[NB*NPIX];       // 64 MB: pass1 output, transposed layout [b][j][i]
__device__ float  g_tzm[NPIX];
__device__ float2 g_tw[512];
__device__ double g_spart[64];
__device__ double g_vpart[64];
__device__ float  g_p1[NB][8][WW];
__device__ float  g_p2[NB][8][WW];
__device__ float  g_fmean[NB];
__device__ float  g_band1[NB][11][WW];
__device__ float  g_band2[NB][11][WW];
__device__ float  g_denom[NB][11][11];
__device__ double g_cc[NB][11][11];
__device__ float2 g_phx[NB][512];
__device__ float2 g_phy[NB][512];

// ---------------- complex helpers -------------------------------------------
__device__ __forceinline__ float2 cmulf(float2 a, float2 b){
  return make_float2(a.x*b.x - a.y*b.y, a.x*b.y + a.y*b.x);
}
__device__ __forceinline__ float2 caddf(float2 a, float2 b){ return make_float2(a.x+b.x, a.y+b.y); }
__device__ __forceinline__ float2 csubf(float2 a, float2 b){ return make_float2(a.x-b.x, a.y-b.y); }
__device__ __forceinline__ float2 mulnegi(float2 a){ return make_float2(a.y, -a.x); }

__device__ __forceinline__ void dft8(float2 a[8]){
  const float RT = 0.70710678118654752440f;
  float2 s0=caddf(a[0],a[4]), s1=caddf(a[1],a[5]), s2=caddf(a[2],a[6]), s3=caddf(a[3],a[7]);
  float2 d0=csubf(a[0],a[4]), d1=csubf(a[1],a[5]), d2=csubf(a[2],a[6]), d3=csubf(a[3],a[7]);
  d1 = cmulf(d1, make_float2( RT,-RT));
  d2 = mulnegi(d2);
  d3 = cmulf(d3, make_float2(-RT,-RT));
  float2 p0=caddf(s0,s2), p1=caddf(s1,s3), m0=csubf(s0,s2), m1=mulnegi(csubf(s1,s3));
  float2 q0=caddf(d0,d2), q1=caddf(d1,d3), n0=csubf(d0,d2), n1=mulnegi(csubf(d1,d3));
  a[0]=caddf(p0,p1); a[4]=csubf(p0,p1); a[2]=caddf(m0,m1); a[6]=csubf(m0,m1);
  a[1]=caddf(q0,q1); a[5]=csubf(q0,q1); a[3]=caddf(n0,n1); a[7]=csubf(n0,n1);
}

template<int L>
__device__ __forceinline__ void stage_load(const float* re, const float* im,
                                           const float2* tw, float2 a[8], int t){
  #pragma unroll
  for (int r = 0; r < 8; r++){
    int i = t + 64*r;
    a[r] = make_float2(re[SK(i)], im[SK(i)]);
  }
  if (L > 1){
    int jm = t % L;
    #pragma unroll
    for (int r = 1; r < 8; r++){
      float2 w = tw[(jm * r * (64/L)) & 511];
      a[r] = cmulf(a[r], w);
    }
  }
}

template<int L>
__device__ __forceinline__ void stage_store(float* re, float* im, const float2 a[8], int t){
  int jd = t / L, jm = t % L;
  #pragma unroll
  for (int r = 0; r < 8; r++){
    int i = jd*8*L + jm + L*r;
    re[SK(i)] = a[r].x; im[SK(i)] = a[r].y;
  }
}

// Full 512-pt forward FFT on registers (a[r] = x[t+64r] in, X[t+64r] out).
__device__ __forceinline__ void fft512(float2 a[8], float* re, float* im,
                                       const float2* stw, int t){
  dft8(a);
  stage_store<1>(re, im, a, t);
  __syncthreads();
  stage_load<8>(re, im, stw, a, t);
  dft8(a);
  __syncthreads();
  stage_store<8>(re, im, a, t);
  __syncthreads();
  stage_load<64>(re, im, stw, a, t);
  dft8(a);
}

// ---------------- init: twiddles + zero cc accumulators ----------------------
__global__ void k_init(){
  int t = threadIdx.x;
  if (t < 512){
    double ang = -2.0 * 3.14159265358979323846 * (double)t / 512.0;
    g_tw[t] = make_float2((float)cos(ang), (float)sin(ang));
  }
  double* cc = &g_cc[0][0][0];
  for (int i = t; i < NB*121; i += blockDim.x) cc[i] = 0.0;
}

// ---------------- template stats (block partials, no global atomics) ---------
__global__ void k_tsum(const float* __restrict__ tpl){
  double s = 0.0;
  for (int i = blockIdx.x*blockDim.x + threadIdx.x; i < NPIX; i += gridDim.x*blockDim.x)
    s += (double)tpl[i];
  __shared__ double sd[256];
  sd[threadIdx.x] = s; __syncthreads();
  for (int o = 128; o; o >>= 1){ if (threadIdx.x < o) sd[threadIdx.x] += sd[threadIdx.x+o]; __syncthreads(); }
  if (threadIdx.x == 0) g_spart[blockIdx.x] = sd[0];
}

__global__ void k_tzm(const float* __restrict__ tpl){
  __shared__ float smean;
  if (threadIdx.x == 0){
    double s = 0.0;
    for (int k = 0; k < 64; k++) s += g_spart[k];
    smean = (float)(s / (double)NPIX);
  }
  __syncthreads();
  float mean = smean;
  double s = 0.0;
  for (int i = blockIdx.x*blockDim.x + threadIdx.x; i < NPIX; i += gridDim.x*blockDim.x){
    float z = tpl[i] - mean;
    g_tzm[i] = z;
    s += (double)(z*z);
  }
  __shared__ double sd[256];
  sd[threadIdx.x] = s; __syncthreads();
  for (int o = 128; o; o >>= 1){ if (threadIdx.x < o) sd[threadIdx.x] += sd[threadIdx.x+o]; __syncthreads(); }
  if (threadIdx.x == 0) g_vpart[blockIdx.x] = sd[0];
}

// ---------------- per-frame partial column sums (high parallelism) -----------
__global__ void k_frame1(const float* __restrict__ fr){
  int b = blockIdx.x, ry = blockIdx.y;
  int j = threadIdx.x;
  const float* xb = fr + (size_t)b*NPIX + (size_t)ry*64*WW;
  float s1 = 0.f, s2 = 0.f;
  #pragma unroll 8
  for (int i = 0; i < 64; i++){
    float v = xb[(size_t)i*WW + j];
    s1 += v; s2 = fmaf(v, v, s2);
  }
  g_p1[b][ry][j] = s1;
  g_p2[b][ry][j] = s2;
}

// ---------------- combine: band sums + frame mean -----------------------------
__global__ void k_frame2(const float* __restrict__ fr){
  int b = blockIdx.x;
  int j = threadIdx.x;
  const float* xb = fr + (size_t)b*NPIX;
  float s1 = 0.f, s2 = 0.f;
  #pragma unroll
  for (int ry = 0; ry < 8; ry++){ s1 += g_p1[b][ry][j]; s2 += g_p2[b][ry][j]; }
  float topv[10], botv[10];
  #pragma unroll
  for (int i = 0; i < 10; i++) topv[i] = xb[(size_t)i*WW + j];
  #pragma unroll
  for (int i = 0; i < 10; i++) botv[i] = xb[(size_t)(502+i)*WW + j];
  float bs1[11], bs2[11];
  bs1[10] = 0.f; bs2[10] = 0.f;
  #pragma unroll
  for (int m = 9; m >= 0; m--){
    bs1[m] = bs1[m+1] + botv[m];
    bs2[m] = bs2[m+1] + botv[m]*botv[m];
  }
  float tp1 = 0.f, tp2 = 0.f;
  #pragma unroll
  for (int p = 0; p < 11; p++){
    g_band1[b][p][j] = s1 - tp1 - bs1[p];
    g_band2[b][p][j] = s2 - tp2 - bs2[p];
    if (p < 10){ tp1 += topv[p]; tp2 += topv[p]*topv[p]; }
  }
  __shared__ float sd[512];
  sd[j] = s1; __syncthreads();
  for (int o = 256; o; o >>= 1){ if (j < o) sd[j] += sd[j+o]; __syncthreads(); }
  if (j == 0) g_fmean[b] = sd[0] / (float)NPIX;
}

// ---------------- denominator ---------------------------------------------
__global__ void k_denom(){
  int b = blockIdx.x;
  int t = threadIdx.x;
  if (t >= 121) return;
  double tv = 0.0;
  for (int k = 0; k < 64; k++) tv += g_vpart[k];
  int p = t / 11, q = t % 11;
  float s1 = 0.f, s2 = 0.f;
  for (int j = q; j < q + 502; j++){
    s1 += g_band1[b][p][j];
    s2 += g_band2[b][p][j];
  }
  float ls  = s1 * INV_A;
  float lsq = s2 * INV_A;
  float var = lsq - ls*ls*INV_A + EPSV;
  if (var < 0.f) var = 0.f;
  float tvar = (float)tv + EPSV;
  g_denom[b][p][q] = sqrtf(tvar * var);
}

// ---------------- direct circular cross-correlation (121 shifts) -------------
// block = 128 threads (4 warps), covers 4 frame rows, all 512 cols.
// warp w owns dxi set {w, w+4, w+8}. Swizzled smem: phys(c)=c+(c>>4) (conflict-free
// for lane stride 16 since gcd(17,32)=1).
__global__ void k_cc(const float* __restrict__ fr){
  __shared__ float sx[4*544];          // 8.7 KB
  __shared__ float st[14*560];         // 31.4 KB (also reused as reduce scratch)
  int b  = blockIdx.y;
  int r0 = blockIdx.x * 4;
  int tid = threadIdx.x;               // 128
  float fm = g_fmean[b];
  const float* xb = fr + (size_t)b*NPIX;
  for (int e = tid; e < 4*512; e += 128){
    int i = e >> 9, c = e & 511;
    sx[i*544 + c + (c>>4)] = xb[(size_t)(r0+i)*WW + c] - fm;
  }
  for (int e = tid; e < 14*522; e += 128){
    int rr = e / 522, c = e - rr*522;
    int gi = (r0 - 5 + rr) & 511;
    int gj = (c - 5) & 511;
    st[rr*560 + c + (c>>4)] = g_tzm[gi*WW + gj];
  }
  __syncthreads();
  int lane = tid & 31, warp = tid >> 5;
  int nd = (warp == 3) ? 2 : 3;
  int j0 = lane * 16;
  float acc[3][11];
  #pragma unroll
  for (int s = 0; s < 3; s++)
    #pragma unroll
    for (int d = 0; d < 11; d++) acc[s][d] = 0.f;
  #pragma unroll
  for (int il = 0; il < 4; il++){
    float xv[16];
    #pragma unroll
    for (int u = 0; u < 16; u++){ int c = j0 + u; xv[u] = sx[il*544 + c + (c>>4)]; }
    #pragma unroll
    for (int s = 0; s < 3; s++){
      if (s < nd){
        int dxi = warp + 4*s;
        int trow = il - dxi + 10;          // always in [0,13]
        float tv[26];
        #pragma unroll
        for (int u = 0; u < 26; u++){ int c = j0 + u; tv[u] = st[trow*560 + c + (c>>4)]; }
        #pragma unroll
        for (int d = 0; d < 11; d++)
          #pragma unroll
          for (int u = 0; u < 16; u++)
            acc[s][d] = fmaf(xv[u], tv[u + 10 - d], acc[s][d]);
      }
    }
  }
  // reduction: smem transpose per warp (pitch 37 -> conflict-free), no shuffles
  __syncthreads();                       // everyone done reading st
  float* red = st + warp * (32*37);      // 4*1184 = 4736 floats <= 7840 available
  #pragma unroll
  for (int k = 0; k < 33; k++)
    red[lane*37 + k] = acc[k/11][k - (k/11)*11];
  __syncwarp();
  #pragma unroll
  for (int rnd = 0; rnd < 2; rnd++){
    int L = lane + 32*rnd;
    if (L < nd*11){
      float s = 0.f;
      #pragma unroll
      for (int l = 0; l < 32; l++) s += red[l*37 + L];
      int dxi = warp + 4*(L/11);
      atomicAdd(&g_cc[b][dxi][L - (L/11)*11], (double)s);
    }
  }
}

// ---------------- argmax + log-parabola + phase tables (merged) ---------------
__global__ void k_shiftphase(){   // grid 32, block 512
  __shared__ float ncc[121];
  __shared__ float s_shx, s_shy;
  int b = blockIdx.x, t = threadIdx.x;
  if (t < 121){
    float num = (float)fabs(g_cc[b][t/11][t%11]);
    float den = g_denom[b][t/11][t%11];
    float v = num / den;
    if (isnan(v)) v = 0.f;
    ncc[t] = v;
  }
  __syncthreads();
  if (t == 0){
    float best = -1e30f; int am = 0;
    for (int k = 0; k < 121; k++){ if (ncc[k] > best){ best = ncc[k]; am = k; } }
    int xi = am / 11, yi = am % 11;
    float shx = -(float)(xi - 5);
    float shy = -(float)(yi - 5);
    int xm = xi - 1; if (xm < 0) xm += 11;   // jnp negative index wraps
    int xp = xi + 1; if (xp > 10) xp = 10;   // jnp OOB gather clamps
    int ym = yi - 1; if (ym < 0) ym += 11;
    int yp = yi + 1; if (yp > 10) yp = 10;
    float l0  = logf(ncc[xi*11 + yi]);
    float lxm = logf(ncc[xm*11 + yi]);
    float lxp = logf(ncc[xp*11 + yi]);
    float lym = logf(ncc[xi*11 + ym]);
    float lyp = logf(ncc[xi*11 + yp]);
    shx -= (lxm - lxp) / (2.f*lxm - 4.f*l0 + 2.f*lxp);
    shy -= (lym - lyp) / (2.f*lym - 4.f*l0 + 2.f*lyp);
    s_shx = shx; s_shy = shy;
  }
  __syncthreads();
  float nr = (t < 256) ? (float)t : (float)(t - 512);
  float2 py, px;
  sincospif(-s_shy * nr * (1.f/256.f), &py.y, &py.x);
  sincospif(-s_shx * nr * (1.f/256.f), &px.y, &px.x);
  g_phy[b][t] = py;
  g_phx[b][t] = px;
}

// ---------------- pass 1: FFT rows along j, write TRANSPOSED complex ----------
__global__ void k_pass1(const float* __restrict__ fr){
  __shared__ float sre[4][SKN], sim[4][SKN];
  __shared__ float2 stw[512];
  int tid = threadIdx.x;
  int rl  = tid >> 6;
  int t   = tid & 63;
  int bi  = blockIdx.x;            // 0..4095
  int b   = bi >> 7;
  int i0  = (bi & 127) * 4;
  const float* rin = fr + ((size_t)b*512 + i0 + rl) * 512;
  const float2* ph = &g_phy[b][0];

  for (int i = tid; i < 512; i += 256) stw[i] = g_tw[i];

  float* re = sre[rl]; float* im = sim[rl];
  float2 a[8];
  #pragma unroll
  for (int r = 0; r < 8; r++) a[r] = make_float2(rin[t + 64*r], 0.f);
  __syncthreads();   // stw ready
  fft512(a, re, im, stw, t);
  #pragma unroll
  for (int r = 0; r < 8; r++){
    float2 p = ph[t + 64*r];
    float xr = a[r].x*p.x - a[r].y*p.y;
    float xi = a[r].x*p.y + a[r].y*p.x;
    a[r] = make_float2(xr * (1.f/512.f), -xi * (1.f/512.f));   // conj + scale
  }
  __syncthreads();
  fft512(a, re, im, stw, t);
  __syncthreads();   // all reads done before overwrite
  // store conj(result) to smem, then transposed coalesced-sector write
  #pragma unroll
  for (int r = 0; r < 8; r++){
    int i = t + 64*r;
    re[SK(i)] = a[r].x;
    im[SK(i)] = -a[r].y;
  }
  __syncthreads();
  for (int idx = tid; idx < 512; idx += 256){
    float4 w1 = make_float4(sre[0][SK(idx)], sim[0][SK(idx)], sre[1][SK(idx)], sim[1][SK(idx)]);
    float4 w2 = make_float4(sre[2][SK(idx)], sim[2][SK(idx)], sre[3][SK(idx)], sim[3][SK(idx)]);
    float4* op = reinterpret_cast<float4*>(g_z2 + ((size_t)b*512 + idx)*512 + i0);
    op[0] = w1; op[1] = w2;
  }
}

// ---------------- pass 2: FFT rows along i (transposed data), real out --------
__global__ void k_pass2(float* __restrict__ out){
  __shared__ float sre[4][SKN], sim[4][SKN];
  __shared__ float2 stw[512];
  int tid = threadIdx.x;
  int rl  = tid >> 6;
  int t   = tid & 63;
  int grow = blockIdx.x * 4 + rl;          // b*512 + j
  int b = grow >> 9;
  const float2* rin = g_z2 + (size_t)grow * 512;
  float* rout       = out + (size_t)grow * 512;   // out[b, j*512 + i]
  const float2* ph  = &g_phx[b][0];

  for (int i = tid; i < 512; i += 256) stw[i] = g_tw[i];

  float* re = sre[rl]; float* im = sim[rl];
  float2 a[8];
  #pragma unroll
  for (int r = 0; r < 8; r++) a[r] = rin[t + 64*r];
  __syncthreads();   // stw ready
  fft512(a, re, im, stw, t);
  #pragma unroll
  for (int r = 0; r < 8; r++){
    float2 p = ph[t + 64*r];
    float xr = a[r].x*p.x - a[r].y*p.y;
    float xi = a[r].x*p.y + a[r].y*p.x;
    a[r] = make_float2(xr * (1.f/512.f), -xi * (1.f/512.f));   // conj + scale
  }
  __syncthreads();
  fft512(a, re, im, stw, t);
  #pragma unroll
  for (int r = 0; r < 8; r++) rout[t + 64*r] = a[r].x;   // Re(conj(z)) = z.x
}

// ---------------- launcher ----------------------------------------------------
extern "C" void kernel_launch(void* const* d_in, const int* in_sizes, int n_in,
                              void* d_out, int out_size){
  const float* fr  = (const float*)d_in[0];
  const float* tpl = (const float*)d_in[1];
  if (n_in >= 2 && in_sizes[0] < in_sizes[1]){
    fr  = (const float*)d_in[1];
    tpl = (const float*)d_in[0];
  }
  float* out = (float*)d_out;
  k_init<<<1, 512>>>();
  k_tsum<<<64, 256>>>(tpl);
  k_tzm<<<64, 256>>>(tpl);
  k_frame1<<<dim3(32, 8), 512>>>(fr);
  k_frame2<<<32, 512>>>(fr);
  k_cc<<<dim3(128, 32), 128>>>(fr);
  k_denom<<<32, 128>>>();
  k_shiftphase<<<32, 512>>>();
  k_pass1<<<4096, 256>>>(fr);
  k_pass2<<<4096, 256>>>(out);
}

// round 5
// speedup vs baseline: 2.3636x; 1.5039x over previous
#include <cuda_runtime.h>
#include <math.h>

#define HH 512
#define WW 512
#define NB 32
#define NPIX (HH*WW)
#define EPSV 1e-8f
#define INV_A (1.0f/252004.0f)   // 1/(502*502)
#define SKN 528
#define SK(i) ((i) + ((i) >> 5))
#define STPITCH 656
#define SW(c) ((c) + 4*((c)>>4))

// ---------------- static device storage --------------------------------------
__device__ float  g_yr[NB*NPIX];       // 32 MB: real intermediate, layout [b][j][i]
__device__ float  g_tzm[NPIX];
__device__ float2 g_tw[512];
__device__ double g_spart[64];
__device__ double g_vpart[64];
__device__ double g_zpart[64];
__device__ float  g_p1[NB][8][WW];
__device__ float  g_p2[NB][8][WW];
__device__ float  g_p3[NB][8][WW];
__device__ float  g_fmean[NB];
__device__ float  g_T[NB];
__device__ float  g_band1[NB][11][WW];
__device__ float  g_band2[NB][11][WW];
__device__ double g_cc[NB][11][11];
__device__ float  g_nx[NB], g_ny[NB], g_corr[NB];
__device__ float2 g_phx[NB][512];
__device__ float2 g_phy[NB][512];

// ---------------- complex helpers --------------------------------------------
__device__ __forceinline__ float2 cmulf(float2 a, float2 b){
  return make_float2(a.x*b.x - a.y*b.y, a.x*b.y + a.y*b.x);
}
__device__ __forceinline__ float2 caddf(float2 a, float2 b){ return make_float2(a.x+b.x, a.y+b.y); }
__device__ __forceinline__ float2 csubf(float2 a, float2 b){ return make_float2(a.x-b.x, a.y-b.y); }
__device__ __forceinline__ float2 mulnegi(float2 a){ return make_float2(a.y, -a.x); }

__device__ __forceinline__ void dft8(float2 a[8]){
  const float RT = 0.70710678118654752440f;
  float2 s0=caddf(a[0],a[4]), s1=caddf(a[1],a[5]), s2=caddf(a[2],a[6]), s3=caddf(a[3],a[7]);
  float2 d0=csubf(a[0],a[4]), d1=csubf(a[1],a[5]), d2=csubf(a[2],a[6]), d3=csubf(a[3],a[7]);
  d1 = cmulf(d1, make_float2( RT,-RT));
  d2 = mulnegi(d2);
  d3 = cmulf(d3, make_float2(-RT,-RT));
  float2 p0=caddf(s0,s2), p1=caddf(s1,s3), m0=csubf(s0,s2), m1=mulnegi(csubf(s1,s3));
  float2 q0=caddf(d0,d2), q1=caddf(d1,d3), n0=csubf(d0,d2), n1=mulnegi(csubf(d1,d3));
  a[0]=caddf(p0,p1); a[4]=csubf(p0,p1); a[2]=caddf(m0,m1); a[6]=csubf(m0,m1);
  a[1]=caddf(q0,q1); a[5]=csubf(q0,q1); a[3]=caddf(n0,n1); a[7]=csubf(n0,n1);
}

template<int L>
__device__ __forceinline__ void stage_load(const float* re, const float* im,
                                           const float2* tw, float2 a[8], int t){
  #pragma unroll
  for (int r = 0; r < 8; r++){
    int i = t + 64*r;
    a[r] = make_float2(re[SK(i)], im[SK(i)]);
  }
  if (L > 1){
    int jm = t % L;
    #pragma unroll
    for (int r = 1; r < 8; r++){
      float2 w = tw[(jm * r * (64/L)) & 511];
      a[r] = cmulf(a[r], w);
    }
  }
}

template<int L>
__device__ __forceinline__ void stage_store(float* re, float* im, const float2 a[8], int t){
  int jd = t / L, jm = t % L;
  #pragma unroll
  for (int r = 0; r < 8; r++){
    int i = jd*8*L + jm + L*r;
    re[SK(i)] = a[r].x; im[SK(i)] = a[r].y;
  }
}

// Full 512-pt forward FFT on registers (a[r] = x[t+64r] in, X[t+64r] out).
// Caller must guarantee smem idle at entry (a __syncthreads since last smem read).
__device__ __forceinline__ void fft512(float2 a[8], float* re, float* im,
                                       const float2* stw, int t){
  dft8(a);
  stage_store<1>(re, im, a, t);
  __syncthreads();
  stage_load<8>(re, im, stw, a, t);
  dft8(a);
  __syncthreads();
  stage_store<8>(re, im, a, t);
  __syncthreads();
  stage_load<64>(re, im, stw, a, t);
  dft8(a);
}

// ---------------- init: twiddles + zero cc accumulators -----------------------
__global__ void k_init(){
  int t = threadIdx.x;
  if (t < 512){
    double ang = -2.0 * 3.14159265358979323846 * (double)t / 512.0;
    g_tw[t] = make_float2((float)cos(ang), (float)sin(ang));
  }
  double* cc = &g_cc[0][0][0];
  for (int i = t; i < NB*121; i += blockDim.x) cc[i] = 0.0;
}

// ---------------- template stats ----------------------------------------------
__global__ void k_tsum(const float* __restrict__ tpl){
  double s = 0.0;
  for (int i = blockIdx.x*blockDim.x + threadIdx.x; i < NPIX; i += gridDim.x*blockDim.x)
    s += (double)tpl[i];
  __shared__ double sd[256];
  sd[threadIdx.x] = s; __syncthreads();
  for (int o = 128; o; o >>= 1){ if (threadIdx.x < o) sd[threadIdx.x] += sd[threadIdx.x+o]; __syncthreads(); }
  if (threadIdx.x == 0) g_spart[blockIdx.x] = sd[0];
}

__global__ void k_tzm(const float* __restrict__ tpl){
  __shared__ float smean;
  if (threadIdx.x == 0){
    double s = 0.0;
    for (int k = 0; k < 64; k++) s += g_spart[k];
    smean = (float)(s / (double)NPIX);
  }
  __syncthreads();
  float mean = smean;
  double sv = 0.0, sz = 0.0;
  for (int i = blockIdx.x*blockDim.x + threadIdx.x; i < NPIX; i += gridDim.x*blockDim.x){
    float z = tpl[i] - mean;
    g_tzm[i] = z;
    sv += (double)(z*z);
    sz += (double)z;
  }
  __shared__ double sd[256], sd2[256];
  sd[threadIdx.x] = sv; sd2[threadIdx.x] = sz; __syncthreads();
  for (int o = 128; o; o >>= 1){
    if (threadIdx.x < o){ sd[threadIdx.x] += sd[threadIdx.x+o]; sd2[threadIdx.x] += sd2[threadIdx.x+o]; }
    __syncthreads();
  }
  if (threadIdx.x == 0){ g_vpart[blockIdx.x] = sd[0]; g_zpart[blockIdx.x] = sd2[0]; }
}

// ---------------- per-frame partial column sums (+ checkerboard) --------------
__global__ void k_frame1(const float* __restrict__ fr){
  int b = blockIdx.x, ry = blockIdx.y;
  int j = threadIdx.x;
  const float* xb = fr + (size_t)b*NPIX + (size_t)ry*64*WW;
  float s1 = 0.f, s2 = 0.f, s3 = 0.f;
  #pragma unroll 8
  for (int i = 0; i < 64; i++){
    float v = xb[(size_t)i*WW + j];
    s1 += v; s2 = fmaf(v, v, s2);
    s3 += (i & 1) ? -v : v;
  }
  g_p1[b][ry][j] = s1;
  g_p2[b][ry][j] = s2;
  g_p3[b][ry][j] = s3;
}

// ---------------- combine: band sums + frame mean + checkerboard total --------
__global__ void k_frame2(const float* __restrict__ fr){
  int b = blockIdx.x;
  int j = threadIdx.x;
  const float* xb = fr + (size_t)b*NPIX;
  float s1 = 0.f, s2 = 0.f, s3 = 0.f;
  #pragma unroll
  for (int ry = 0; ry < 8; ry++){ s1 += g_p1[b][ry][j]; s2 += g_p2[b][ry][j]; s3 += g_p3[b][ry][j]; }
  float topv[10], botv[10];
  #pragma unroll
  for (int i = 0; i < 10; i++) topv[i] = xb[(size_t)i*WW + j];
  #pragma unroll
  for (int i = 0; i < 10; i++) botv[i] = xb[(size_t)(502+i)*WW + j];
  float bs1[11], bs2[11];
  bs1[10] = 0.f; bs2[10] = 0.f;
  #pragma unroll
  for (int m = 9; m >= 0; m--){
    bs1[m] = bs1[m+1] + botv[m];
    bs2[m] = bs2[m+1] + botv[m]*botv[m];
  }
  float tp1 = 0.f, tp2 = 0.f;
  #pragma unroll
  for (int p = 0; p < 11; p++){
    g_band1[b][p][j] = s1 - tp1 - bs1[p];
    g_band2[b][p][j] = s2 - tp2 - bs2[p];
    if (p < 10){ tp1 += topv[p]; tp2 += topv[p]*topv[p]; }
  }
  __shared__ float sd[512], sd2[512];
  sd[j] = s1;
  sd2[j] = (j & 1) ? -s3 : s3;
  __syncthreads();
  for (int o = 256; o; o >>= 1){
    if (j < o){ sd[j] += sd[j+o]; sd2[j] += sd2[j+o]; }
    __syncthreads();
  }
  if (j == 0){ g_fmean[b] = sd[0] / (float)NPIX; g_T[b] = sd2[0]; }
}

// ---------------- direct circular cross-correlation (121 shifts) --------------
// block = 128 threads (4 warps), covers 4 frame rows, all 512 cols.
// x read straight from gmem (float4); template in smem with phys(c)=c+4*(c>>4)
// (20*lane offsets -> conflict-free float4 LDS). No mean subtraction here
// (compensated exactly in k_shiftphase by fmean*Σtzm).
__global__ void k_cc(const float* __restrict__ fr){
  __shared__ float st[14*STPITCH];     // 36.7 KB (also reused as reduce scratch)
  int b  = blockIdx.y;
  int r0 = blockIdx.x * 4;
  int tid = threadIdx.x;               // 128
  for (int e = tid; e < 14*522; e += 128){
    int rr = e / 522, c = e - rr*522;
    int gi = (r0 - 5 + rr) & 511;
    int gj = (c - 5) & 511;
    st[rr*STPITCH + SW(c)] = g_tzm[gi*WW + gj];
  }
  __syncthreads();
  int lane = tid & 31, warp = tid >> 5;
  int nd = (warp == 3) ? 2 : 3;
  int j0 = lane * 16;
  float acc[3][11];
  #pragma unroll
  for (int s = 0; s < 3; s++)
    #pragma unroll
    for (int d = 0; d < 11; d++) acc[s][d] = 0.f;
  const float* xbase = fr + ((size_t)b*512 + r0)*512 + j0;
  #pragma unroll
  for (int il = 0; il < 4; il++){
    float4 xq[4];
    #pragma unroll
    for (int k = 0; k < 4; k++)
      xq[k] = *reinterpret_cast<const float4*>(xbase + (size_t)il*512 + 4*k);
    float xv[16];
    #pragma unroll
    for (int k = 0; k < 4; k++){ xv[4*k]=xq[k].x; xv[4*k+1]=xq[k].y; xv[4*k+2]=xq[k].z; xv[4*k+3]=xq[k].w; }
    #pragma unroll
    for (int s = 0; s < 3; s++){
      if (s < nd){
        int dxi = warp + 4*s;
        int trow = il - dxi + 10;          // always in [0,13]
        const float* base = st + trow*STPITCH + 20*lane;
        float4 tq[7];
        #pragma unroll
        for (int k = 0; k < 4; k++) tq[k] = *reinterpret_cast<const float4*>(base + 4*k);
        #pragma unroll
        for (int k = 0; k < 3; k++) tq[4+k] = *reinterpret_cast<const float4*>(base + 20 + 4*k);
        float tv[28];
        #pragma unroll
        for (int k = 0; k < 7; k++){
          int o = (k < 4) ? 4*k : 16 + 4*(k-4);
          tv[o]=tq[k].x; tv[o+1]=tq[k].y; tv[o+2]=tq[k].z; tv[o+3]=tq[k].w;
        }
        #pragma unroll
        for (int d = 0; d < 11; d++)
          #pragma unroll
          for (int u = 0; u < 16; u++)
            acc[s][d] = fmaf(xv[u], tv[u + 10 - d], acc[s][d]);
      }
    }
  }
  // reduction: smem transpose per warp (pitch 37 -> conflict-free)
  __syncthreads();                       // everyone done reading st
  float* red = st + warp * (32*37);      // 4736 floats <= 14*656
  #pragma unroll
  for (int k = 0; k < 33; k++)
    red[lane*37 + k] = acc[k/11][k - (k/11)*11];
  __syncwarp();
  #pragma unroll
  for (int rnd = 0; rnd < 2; rnd++){
    int L = lane + 32*rnd;
    if (L < nd*11){
      float s = 0.f;
      #pragma unroll
      for (int l = 0; l < 32; l++) s += red[l*37 + L];
      int dxi = warp + 4*(L/11);
      atomicAdd(&g_cc[b][dxi][L - (L/11)*11], (double)s);
    }
  }
}

// ---------------- denom + argmax + log-parabola + phases (merged) -------------
__global__ void k_shiftphase(){   // grid 32, block 512
  __shared__ float part1[484], part2[484];
  __shared__ float ncc[121];
  __shared__ float s_shx, s_shy;
  __shared__ float s_tvar;
  __shared__ float s_corr0;       // fmean*Tz
  int b = blockIdx.x, t = threadIdx.x;
  if (t == 0){
    double tv = 0.0, tz = 0.0;
    for (int k = 0; k < 64; k++){ tv += g_vpart[k]; tz += g_zpart[k]; }
    s_tvar = (float)tv + EPSV;
    s_corr0 = g_fmean[b] * (float)tz;
  }
  // window partial sums: 4 threads per window
  if (t < 484){
    int w = t >> 2, s = t & 3;
    int q = w % 11;
    int j0 = q + 126*s;
    int len = (s == 3) ? 124 : 126;
    const float* b1 = &g_band1[b][w/11][0];
    const float* b2 = &g_band2[b][w/11][0];
    float s1 = 0.f, s2 = 0.f;
    for (int j = j0; j < j0 + len; j++){ s1 += b1[j]; s2 += b2[j]; }
    part1[t] = s1; part2[t] = s2;
  }
  __syncthreads();
  if (t < 121){
    float s1 = part1[4*t] + part1[4*t+1] + part1[4*t+2] + part1[4*t+3];
    float s2 = part2[4*t] + part2[4*t+1] + part2[4*t+2] + part2[4*t+3];
    float ls  = s1 * INV_A;
    float lsq = s2 * INV_A;
    float var = lsq - ls*ls*INV_A + EPSV;
    if (var < 0.f) var = 0.f;
    float den = sqrtf(s_tvar * var);
    float num = fabsf((float)g_cc[b][t/11][t%11] - s_corr0);
    float v = num / den;
    if (isnan(v)) v = 0.f;
    ncc[t] = v;
  }
  __syncthreads();
  if (t == 0){
    float best = -1e30f; int am = 0;
    for (int k = 0; k < 121; k++){ if (ncc[k] > best){ best = ncc[k]; am = k; } }
    int xi = am / 11, yi = am % 11;
    float shx = -(float)(xi - 5);
    float shy = -(float)(yi - 5);
    int xm = xi - 1; if (xm < 0) xm += 11;   // jnp negative index wraps
    int xp = xi + 1; if (xp > 10) xp = 10;   // jnp OOB gather clamps
    int ym = yi - 1; if (ym < 0) ym += 11;
    int yp = yi + 1; if (yp > 10) yp = 10;
    float l0  = logf(ncc[xi*11 + yi]);
    float lxm = logf(ncc[xm*11 + yi]);
    float lxp = logf(ncc[xp*11 + yi]);
    float lym = logf(ncc[xi*11 + ym]);
    float lyp = logf(ncc[xi*11 + yp]);
    shx -= (lxm - lxp) / (2.f*lxm - 4.f*l0 + 2.f*lxp);
    shy -= (lym - lyp) / (2.f*lym - 4.f*l0 + 2.f*lyp);
    s_shx = shx; s_shy = shy;
    float nx = sinpif(shx), ny = sinpif(shy);
    g_nx[b] = nx; g_ny[b] = ny;
    g_corr[b] = nx * ny * g_T[b] * (1.f/262144.f);
  }
  __syncthreads();
  float nr = (t < 256) ? (float)t : (float)(t - 512);
  float2 py, px;
  sincospif(-s_shy * nr * (1.f/256.f), &py.y, &py.x);
  sincospif(-s_shx * nr * (1.f/256.f), &px.y, &px.x);
  g_phy[b][t] = py;
  g_phx[b][t] = px;
}

// ---------------- pass 1: 2 packed real rows per FFT, real transposed output --
__global__ void k_pass1(const float* __restrict__ fr){
  __shared__ float sre[4][SKN], sim[4][SKN];
  __shared__ float2 stw[512];
  __shared__ float2 sv[4];
  int tid = threadIdx.x;
  int g   = tid >> 6;
  int t   = tid & 63;
  int bi  = blockIdx.x;            // 0..2047
  int b   = bi >> 6;               // 64 blocks per frame
  int i0  = (bi & 63) * 8;
  const float* p1 = fr + ((size_t)b*512 + i0 + 2*g) * 512;
  const float* p2 = p1 + 512;
  const float2* ph = &g_phy[b][0];
  float ny = g_ny[b];
  float sg = (t & 1) ? -1.f : 1.f;       // (-1)^j for j = t+64r

  for (int i = tid; i < 512; i += 256) stw[i] = g_tw[i];

  float* re = sre[g]; float* im = sim[g];
  float2 a[8];
  #pragma unroll
  for (int r = 0; r < 8; r++) a[r] = make_float2(p1[t + 64*r], p2[t + 64*r]);
  __syncthreads();   // stw ready
  fft512(a, re, im, stw, t);             // V = F(x1 + i x2)
  if (t == 0) sv[g] = a[4];              // V[256]
  __syncthreads();
  float2 V256 = sv[g];
  float b1 = ny * V256.x * (1.f/512.f);  // beta for row1
  float b2 = ny * V256.y * (1.f/512.f);  // beta for row2
  #pragma unroll
  for (int r = 0; r < 8; r++){           // Q = Py*V, then conj/512 for inverse
    float2 p = ph[t + 64*r];
    float xr = a[r].x*p.x - a[r].y*p.y;
    float xi = a[r].x*p.y + a[r].y*p.x;
    a[r] = make_float2(xr * (1.f/512.f), -xi * (1.f/512.f));
  }
  fft512(a, re, im, stw, t);             // u = conj(result)
  __syncthreads();                       // all smem reads done before overwrite
  // unpack: y1[j] = Re(u) + sg*b2 ; y2[j] = Im(u) - sg*b1 ; Im(u) = -a.y
  #pragma unroll
  for (int r = 0; r < 8; r++){
    int j = t + 64*r;
    re[SK(j)] = a[r].x + sg*b2;
    im[SK(j)] = -a[r].y - sg*b1;
  }
  __syncthreads();
  // transposed coalesced write: g_yr[b][j][i0..i0+7]
  for (int idx = tid; idx < 512; idx += 256){
    float4 w1 = make_float4(sre[0][SK(idx)], sim[0][SK(idx)], sre[1][SK(idx)], sim[1][SK(idx)]);
    float4 w2 = make_float4(sre[2][SK(idx)], sim[2][SK(idx)], sre[3][SK(idx)], sim[3][SK(idx)]);
    float4* op = reinterpret_cast<float4*>(g_yr + ((size_t)b*512 + idx)*512 + i0);
    op[0] = w1; op[1] = w2;
  }
}

// ---------------- pass 2: 2 packed real columns per FFT, final output ---------
__global__ void k_pass2(float* __restrict__ out){
  __shared__ float sre[4][SKN], sim[4][SKN];
  __shared__ float2 stw[512];
  __shared__ float2 sv[4];
  int tid = threadIdx.x;
  int g   = tid >> 6;
  int t   = tid & 63;
  int bi  = blockIdx.x;            // 0..2047
  int b   = bi >> 6;
  int j1  = (bi & 63) * 8 + 2*g;   // even column
  const float* c1 = g_yr + ((size_t)b*512 + j1) * 512;
  const float* c2 = c1 + 512;
  const float2* ph = &g_phx[b][0];
  float nx = g_nx[b];
  float corr = g_corr[b];
  float sg = (t & 1) ? -1.f : 1.f;       // (-1)^i for i = t+64r

  for (int i = tid; i < 512; i += 256) stw[i] = g_tw[i];

  float* re = sre[g]; float* im = sim[g];
  float2 a[8];
  #pragma unroll
  for (int r = 0; r < 8; r++) a[r] = make_float2(c1[t + 64*r], c2[t + 64*r]);
  __syncthreads();   // stw ready
  fft512(a, re, im, stw, t);             // U = F(z1 + i z2)
  if (t == 0) sv[g] = a[4];              // U[256]
  __syncthreads();
  float2 U256 = sv[g];
  float e1 = nx * U256.x * (1.f/512.f) - corr;   // j1 even: sigma_j=+1; j2 odd: -1
  float e2 = nx * U256.y * (1.f/512.f) - corr;
  #pragma unroll
  for (int r = 0; r < 8; r++){           // Q = Px*U, conj/512
    float2 p = ph[t + 64*r];
    float xr = a[r].x*p.x - a[r].y*p.y;
    float xi = a[r].x*p.y + a[r].y*p.x;
    a[r] = make_float2(xr * (1.f/512.f), -xi * (1.f/512.f));
  }
  fft512(a, re, im, stw, t);             // u = conj(result)
  // out1[i] = Re(u) + sg*(c2 - corr); out2[i] = Im(u) - sg*(c1 - corr)
  float* r1 = out + ((size_t)b*512 + j1) * 512;
  float* r2 = r1 + 512;
  #pragma unroll
  for (int r = 0; r < 8; r++){
    int i = t + 64*r;
    r1[i] = a[r].x + sg*e2;
    r2[i] = -a[r].y - sg*e1;
  }
}

// ---------------- launcher -----------------------------------------------------
extern "C" void kernel_launch(void* const* d_in, const int* in_sizes, int n_in,
                              void* d_out, int out_size){
  const float* fr  = (const float*)d_in[0];
  const float* tpl = (const float*)d_in[1];
  if (n_in >= 2 && in_sizes[0] < in_sizes[1]){
    fr  = (const float*)d_in[1];
    tpl = (const float*)d_in[0];
  }
  float* out = (float*)d_out;
  k_init<<<1, 512>>>();
  k_tsum<<<64, 256>>>(tpl);
  k_tzm<<<64, 256>>>(tpl);
  k_frame1<<<dim3(32, 8), 512>>>(fr);
  k_frame2<<<32, 512>>>(fr);
  k_cc<<<dim3(128, 32), 128>>>(fr);
  k_shiftphase<<<32, 512>>>();
  k_pass1<<<2048, 256>>>(fr);
  k_pass2<<<2048, 256>>>(out);
}

// round 6
// speedup vs baseline: 2.6292x; 1.1124x over previous
#include <cuda_runtime.h>
#include <math.h>

#define HH 512
#define WW 512
#define NB 32
#define NPIX (HH*WW)
#define EPSV 1e-8f
#define INV_A (1.0f/252004.0f)   // 1/(502*502)
#define SKN 528
#define SK(i) ((i) + ((i) >> 5))
#define STPITCH 656
#define SW(c) ((c) + 4*((c)>>4))
#define FNB 262144.0

// ---------------- static device storage --------------------------------------
__device__ float  g_yr[NB*NPIX];       // 32 MB real intermediate [b][j][i]
__device__ float  g_p1[NB][32][WW];
__device__ float  g_p2[NB][32][WW];
__device__ float  g_p3[NB][32][WW];
__device__ double g_tq1[32], g_tq2[32];
__device__ float  g_ccp[NB][64][121];  // per-block cc partials (no atomics)
__device__ float  g_nx[NB], g_ny[NB], g_corr[NB];
__device__ float2 g_phx[NB][512];
__device__ float2 g_phy[NB][512];

// ---------------- complex helpers --------------------------------------------
__device__ __forceinline__ float2 cmulf(float2 a, float2 b){
  return make_float2(a.x*b.x - a.y*b.y, a.x*b.y + a.y*b.x);
}
__device__ __forceinline__ float2 caddf(float2 a, float2 b){ return make_float2(a.x+b.x, a.y+b.y); }
__device__ __forceinline__ float2 csubf(float2 a, float2 b){ return make_float2(a.x-b.x, a.y-b.y); }
__device__ __forceinline__ float2 mulnegi(float2 a){ return make_float2(a.y, -a.x); }

__device__ __forceinline__ void dft8(float2 a[8]){
  const float RT = 0.70710678118654752440f;
  float2 s0=caddf(a[0],a[4]), s1=caddf(a[1],a[5]), s2=caddf(a[2],a[6]), s3=caddf(a[3],a[7]);
  float2 d0=csubf(a[0],a[4]), d1=csubf(a[1],a[5]), d2=csubf(a[2],a[6]), d3=csubf(a[3],a[7]);
  d1 = cmulf(d1, make_float2( RT,-RT));
  d2 = mulnegi(d2);
  d3 = cmulf(d3, make_float2(-RT,-RT));
  float2 p0=caddf(s0,s2), p1=caddf(s1,s3), m0=csubf(s0,s2), m1=mulnegi(csubf(s1,s3));
  float2 q0=caddf(d0,d2), q1=caddf(d1,d3), n0=csubf(d0,d2), n1=mulnegi(csubf(d1,d3));
  a[0]=caddf(p0,p1); a[4]=csubf(p0,p1); a[2]=caddf(m0,m1); a[6]=csubf(m0,m1);
  a[1]=caddf(q0,q1); a[5]=csubf(q0,q1); a[3]=caddf(n0,n1); a[7]=csubf(n0,n1);
}

template<int L>
__device__ __forceinline__ void stage_load(const float* re, const float* im,
                                           const float2* tw, float2 a[8], int t){
  #pragma unroll
  for (int r = 0; r < 8; r++){
    int i = t + 64*r;
    a[r] = make_float2(re[SK(i)], im[SK(i)]);
  }
  if (L > 1){
    int jm = t % L;
    #pragma unroll
    for (int r = 1; r < 8; r++){
      float2 w = tw[(jm * r * (64/L)) & 511];
      a[r] = cmulf(a[r], w);
    }
  }
}

template<int L>
__device__ __forceinline__ void stage_store(float* re, float* im, const float2 a[8], int t){
  int jd = t / L, jm = t % L;
  #pragma unroll
  for (int r = 0; r < 8; r++){
    int i = jd*8*L + jm + L*r;
    re[SK(i)] = a[r].x; im[SK(i)] = a[r].y;
  }
}

__device__ __forceinline__ void fft512(float2 a[8], float* re, float* im,
                                       const float2* stw, int t){
  dft8(a);
  stage_store<1>(re, im, a, t);
  __syncthreads();
  stage_load<8>(re, im, stw, a, t);
  dft8(a);
  __syncthreads();
  stage_store<8>(re, im, a, t);
  __syncthreads();
  stage_load<64>(re, im, stw, a, t);
  dft8(a);
}

// ---------------- stats: frame partial sums + template moments ----------------
__global__ void k_stats(const float* __restrict__ fr, const float* __restrict__ tpl){
  __shared__ double sd[512], sq[512];
  int b = blockIdx.x, ry = blockIdx.y;
  int j = threadIdx.x;
  if (b < NB){
    const float* xb = fr + (size_t)b*NPIX + (size_t)ry*16*WW;
    float s1 = 0.f, s2 = 0.f, s3 = 0.f;
    #pragma unroll
    for (int i = 0; i < 16; i++){
      float v = xb[(size_t)i*WW + j];
      s1 += v; s2 = fmaf(v, v, s2);
      s3 += (i & 1) ? -v : v;
    }
    g_p1[b][ry][j] = s1;
    g_p2[b][ry][j] = s2;
    g_p3[b][ry][j] = s3;
  } else {
    const float* tb = tpl + (size_t)ry*16*WW;
    double s = 0.0, q = 0.0;
    #pragma unroll
    for (int i = 0; i < 16; i++){
      float v = tb[(size_t)i*WW + j];
      s += (double)v; q += (double)v*(double)v;
    }
    sd[j] = s; sq[j] = q; __syncthreads();
    for (int o = 256; o; o >>= 1){
      if (j < o){ sd[j] += sd[j+o]; sq[j] += sq[j+o]; }
      __syncthreads();
    }
    if (j == 0){ g_tq1[ry] = sd[0]; g_tq2[ry] = sq[0]; }
  }
}

// ---------------- direct circular cross-correlation (121 shifts) --------------
// block = 128 threads (4 warps), 8 frame rows, all 512 cols.
// raw x, template-2; correction applied in k_shiftphase (exact).
__global__ void __launch_bounds__(128) k_cc(const float* __restrict__ fr,
                                            const float* __restrict__ tpl){
  __shared__ float st[18*STPITCH];     // 46.1 KB (reused as reduce scratch)
  int b  = blockIdx.y;
  int r0 = blockIdx.x * 8;
  int tid = threadIdx.x;               // 128
  for (int e = tid; e < 18*522; e += 128){
    int rr = e / 522, c = e - rr*522;
    int gi = (r0 - 5 + rr) & 511;
    int gj = (c - 5) & 511;
    st[rr*STPITCH + SW(c)] = tpl[gi*WW + gj] - 2.0f;
  }
  __syncthreads();
  int lane = tid & 31, warp = tid >> 5;
  int nd = (warp == 3) ? 2 : 3;
  int j0 = lane * 16;
  float acc[3][11];
  #pragma unroll
  for (int s = 0; s < 3; s++)
    #pragma unroll
    for (int d = 0; d < 11; d++) acc[s][d] = 0.f;
  const float* xbase = fr + ((size_t)b*512 + r0)*512 + j0;
  #pragma unroll 1
  for (int il = 0; il < 8; il++){
    float4 xq[4];
    #pragma unroll
    for (int k = 0; k < 4; k++)
      xq[k] = *reinterpret_cast<const float4*>(xbase + (size_t)il*512 + 4*k);
    float xv[16];
    #pragma unroll
    for (int k = 0; k < 4; k++){ xv[4*k]=xq[k].x; xv[4*k+1]=xq[k].y; xv[4*k+2]=xq[k].z; xv[4*k+3]=xq[k].w; }
    #pragma unroll
    for (int s = 0; s < 3; s++){
      if (s < nd){
        int dxi = warp + 4*s;
        int trow = il - dxi + 10;          // in [0,17]
        const float* base = st + trow*STPITCH + 20*lane;
        float4 tq[7];
        #pragma unroll
        for (int k = 0; k < 4; k++) tq[k] = *reinterpret_cast<const float4*>(base + 4*k);
        #pragma unroll
        for (int k = 0; k < 3; k++) tq[4+k] = *reinterpret_cast<const float4*>(base + 20 + 4*k);
        float tv[28];
        #pragma unroll
        for (int k = 0; k < 7; k++){
          int o = (k < 4) ? 4*k : 16 + 4*(k-4);
          tv[o]=tq[k].x; tv[o+1]=tq[k].y; tv[o+2]=tq[k].z; tv[o+3]=tq[k].w;
        }
        #pragma unroll
        for (int d = 0; d < 11; d++)
          #pragma unroll
          for (int u = 0; u < 16; u++)
            acc[s][d] = fmaf(xv[u], tv[u + 10 - d], acc[s][d]);
      }
    }
  }
  // reduction: smem transpose per warp (pitch 37 -> conflict-free)
  __syncthreads();
  float* red = st + warp * (32*37);
  #pragma unroll
  for (int k = 0; k < 33; k++)
    red[lane*37 + k] = acc[k/11][k - (k/11)*11];
  __syncwarp();
  #pragma unroll
  for (int rnd = 0; rnd < 2; rnd++){
    int L = lane + 32*rnd;
    if (L < nd*11){
      float s = 0.f;
      #pragma unroll
      for (int l = 0; l < 32; l++) s += red[l*37 + L];
      int dxi = warp + 4*(L/11);
      g_ccp[b][blockIdx.x][dxi*11 + (L - (L/11)*11)] = s;
    }
  }
}

// ---------------- bands + denom + cc-combine + argmax + parabola + phases -----
__global__ void __launch_bounds__(512) k_shiftphase(const float* __restrict__ fr){
  __shared__ float sb1[11][512];
  __shared__ float sb2[11][512];
  __shared__ float part1[242], part2[242];
  __shared__ float ncc[121];
  __shared__ float wp1[16], wp2[16];
  __shared__ float s_shx, s_shy, s_fm, s_T;
  __shared__ double s_tm, s_tvar;
  int b = blockIdx.x, t = threadIdx.x;
  if (t == 0){
    double S = 0.0, Q = 0.0;
    #pragma unroll
    for (int k = 0; k < 32; k++){ S += g_tq1[k]; Q += g_tq2[k]; }
    double tm = S / FNB;
    s_tm = tm;
    s_tvar = Q - FNB*tm*tm;
  }
  // column sums from strip partials
  float s1 = 0.f, s2 = 0.f, s3 = 0.f;
  #pragma unroll
  for (int ry = 0; ry < 32; ry++){
    s1 += g_p1[b][ry][t]; s2 += g_p2[b][ry][t]; s3 += g_p3[b][ry][t];
  }
  // edge rows for band sums
  const float* xb = fr + (size_t)b*NPIX;
  float topv[10], botv[10];
  #pragma unroll
  for (int i = 0; i < 10; i++) topv[i] = xb[(size_t)i*WW + t];
  #pragma unroll
  for (int i = 0; i < 10; i++) botv[i] = xb[(size_t)(502+i)*WW + t];
  float bs1[11], bs2[11];
  bs1[10] = 0.f; bs2[10] = 0.f;
  #pragma unroll
  for (int m = 9; m >= 0; m--){
    bs1[m] = bs1[m+1] + botv[m];
    bs2[m] = bs2[m+1] + botv[m]*botv[m];
  }
  float tp1 = 0.f, tp2 = 0.f;
  #pragma unroll
  for (int p = 0; p < 11; p++){
    sb1[p][t] = s1 - tp1 - bs1[p];
    sb2[p][t] = s2 - tp2 - bs2[p];
    if (p < 10){ tp1 += topv[p]; tp2 += topv[p]*topv[p]; }
  }
  // frame mean + checkerboard via warp reduce
  float rsum = s1;
  float csum = (t & 1) ? -s3 : s3;
  #pragma unroll
  for (int o = 16; o; o >>= 1){
    rsum += __shfl_down_sync(0xffffffffu, rsum, o);
    csum += __shfl_down_sync(0xffffffffu, csum, o);
  }
  if ((t & 31) == 0){ wp1[t>>5] = rsum; wp2[t>>5] = csum; }
  __syncthreads();
  if (t == 0){
    float a = 0.f, c = 0.f;
    #pragma unroll
    for (int k = 0; k < 16; k++){ a += wp1[k]; c += wp2[k]; }
    s_fm = a / (float)NPIX;
    s_T = c;
  }
  // window partial sums (2 segments of 251)
  if (t < 242){
    int w = t >> 1, s = t & 1;
    int p = w / 11, q = w - 11*p;
    int j0 = q + 251*s;
    float a = 0.f, c = 0.f;
    for (int j = j0; j < j0 + 251; j++){ a += sb1[p][j]; c += sb2[p][j]; }
    part1[t] = a; part2[t] = c;
  }
  __syncthreads();
  if (t < 121){
    float w1 = part1[2*t] + part1[2*t+1];
    float w2 = part2[2*t] + part2[2*t+1];
    float ls  = w1 * INV_A;
    float lsq = w2 * INV_A;
    float var = lsq - ls*ls*INV_A + EPSV;
    if (var < 0.f) var = 0.f;
    float den = sqrtf(((float)s_tvar + EPSV) * var);
    float ccs = 0.f;
    for (int k = 0; k < 64; k++) ccs += g_ccp[b][k][t];
    double corr = (double)s_fm * FNB * (s_tm - 2.0);   // N*fm*(tm-2)
    float num = fabsf((float)((double)ccs - corr));
    float v = num / den;
    if (isnan(v)) v = 0.f;
    ncc[t] = v;
  }
  __syncthreads();
  if (t == 0){
    float best = -1e30f; int am = 0;
    for (int k = 0; k < 121; k++){ if (ncc[k] > best){ best = ncc[k]; am = k; } }
    int xi = am / 11, yi = am % 11;
    float shx = -(float)(xi - 5);
    float shy = -(float)(yi - 5);
    int xm = xi - 1; if (xm < 0) xm += 11;   // jnp negative index wraps
    int xp = xi + 1; if (xp > 10) xp = 10;   // jnp OOB gather clamps
    int ym = yi - 1; if (ym < 0) ym += 11;
    int yp = yi + 1; if (yp > 10) yp = 10;
    float l0  = logf(ncc[xi*11 + yi]);
    float lxm = logf(ncc[xm*11 + yi]);
    float lxp = logf(ncc[xp*11 + yi]);
    float lym = logf(ncc[xi*11 + ym]);
    float lyp = logf(ncc[xi*11 + yp]);
    shx -= (lxm - lxp) / (2.f*lxm - 4.f*l0 + 2.f*lxp);
    shy -= (lym - lyp) / (2.f*lym - 4.f*l0 + 2.f*lyp);
    s_shx = shx; s_shy = shy;
    float nx = sinpif(shx), ny = sinpif(shy);
    g_nx[b] = nx; g_ny[b] = ny;
    g_corr[b] = nx * ny * s_T * (1.f/262144.f);
  }
  __syncthreads();
  float nr = (t < 256) ? (float)t : (float)(t - 512);
  float2 py, px;
  sincospif(-s_shy * nr * (1.f/256.f), &py.y, &py.x);
  sincospif(-s_shx * nr * (1.f/256.f), &px.y, &px.x);
  g_phy[b][t] = py;
  g_phx[b][t] = px;
}

// ---------------- pass 1: 2 packed real rows per FFT, real transposed output --
__global__ void k_pass1(const float* __restrict__ fr){
  __shared__ float sre[4][SKN], sim[4][SKN];
  __shared__ float2 stw[512];
  __shared__ float2 sv[4];
  int tid = threadIdx.x;
  int g   = tid >> 6;
  int t   = tid & 63;
  int bi  = blockIdx.x;            // 0..2047
  int b   = bi >> 6;
  int i0  = (bi & 63) * 8;
  const float* p1 = fr + ((size_t)b*512 + i0 + 2*g) * 512;
  const float* p2 = p1 + 512;
  const float2* ph = &g_phy[b][0];
  float ny = g_ny[b];
  float sg = (t & 1) ? -1.f : 1.f;

  for (int i = tid; i < 512; i += 256){
    float2 w;
    sincospif(-(float)i * (1.f/256.f), &w.y, &w.x);
    stw[i] = w;
  }

  float* re = sre[g]; float* im = sim[g];
  float2 a[8];
  #pragma unroll
  for (int r = 0; r < 8; r++) a[r] = make_float2(p1[t + 64*r], p2[t + 64*r]);
  __syncthreads();   // stw ready
  fft512(a, re, im, stw, t);             // V = F(x1 + i x2)
  if (t == 0) sv[g] = a[4];              // V[256]
  __syncthreads();
  float2 V256 = sv[g];
  float b1 = ny * V256.x * (1.f/512.f);
  float b2 = ny * V256.y * (1.f/512.f);
  #pragma unroll
  for (int r = 0; r < 8; r++){
    float2 p = ph[t + 64*r];
    float xr = a[r].x*p.x - a[r].y*p.y;
    float xi = a[r].x*p.y + a[r].y*p.x;
    a[r] = make_float2(xr * (1.f/512.f), -xi * (1.f/512.f));
  }
  fft512(a, re, im, stw, t);
  __syncthreads();
  #pragma unroll
  for (int r = 0; r < 8; r++){
    int j = t + 64*r;
    re[SK(j)] = a[r].x + sg*b2;
    im[SK(j)] = -a[r].y - sg*b1;
  }
  __syncthreads();
  for (int idx = tid; idx < 512; idx += 256){
    float4 w1 = make_float4(sre[0][SK(idx)], sim[0][SK(idx)], sre[1][SK(idx)], sim[1][SK(idx)]);
    float4 w2 = make_float4(sre[2][SK(idx)], sim[2][SK(idx)], sre[3][SK(idx)], sim[3][SK(idx)]);
    float4* op = reinterpret_cast<float4*>(g_yr + ((size_t)b*512 + idx)*512 + i0);
    op[0] = w1; op[1] = w2;
  }
}

// ---------------- pass 2: 2 packed real columns per FFT, final output ---------
__global__ void k_pass2(float* __restrict__ out){
  __shared__ float sre[4][SKN], sim[4][SKN];
  __shared__ float2 stw[512];
  __shared__ float2 sv[4];
  int tid = threadIdx.x;
  int g   = tid >> 6;
  int t   = tid & 63;
  int bi  = blockIdx.x;
  int b   = bi >> 6;
  int j1  = (bi & 63) * 8 + 2*g;
  const float* c1 = g_yr + ((size_t)b*512 + j1) * 512;
  const float* c2 = c1 + 512;
  const float2* ph = &g_phx[b][0];
  float nx = g_nx[b];
  float corr = g_corr[b];
  float sg = (t & 1) ? -1.f : 1.f;

  for (int i = tid; i < 512; i += 256){
    float2 w;
    sincospif(-(float)i * (1.f/256.f), &w.y, &w.x);
    stw[i] = w;
  }

  float* re = sre[g]; float* im = sim[g];
  float2 a[8];
  #pragma unroll
  for (int r = 0; r < 8; r++) a[r] = make_float2(c1[t + 64*r], c2[t + 64*r]);
  __syncthreads();
  fft512(a, re, im, stw, t);
  if (t == 0) sv[g] = a[4];
  __syncthreads();
  float2 U256 = sv[g];
  float e1 = nx * U256.x * (1.f/512.f) - corr;
  float e2 = nx * U256.y * (1.f/512.f) - corr;
  #pragma unroll
  for (int r = 0; r < 8; r++){
    float2 p = ph[t + 64*r];
    float xr = a[r].x*p.x - a[r].y*p.y;
    float xi = a[r].x*p.y + a[r].y*p.x;
    a[r] = make_float2(xr * (1.f/512.f), -xi * (1.f/512.f));
  }
  fft512(a, re, im, stw, t);
  float* r1 = out + ((size_t)b*512 + j1) * 512;
  float* r2 = r1 + 512;
  #pragma unroll
  for (int r = 0; r < 8; r++){
    int i = t + 64*r;
    r1[i] = a[r].x + sg*e2;
    r2[i] = -a[r].y - sg*e1;
  }
}

// ---------------- launcher -----------------------------------------------------
extern "C" void kernel_launch(void* const* d_in, const int* in_sizes, int n_in,
                              void* d_out, int out_size){
  const float* fr  = (const float*)d_in[0];
  const float* tpl = (const float*)d_in[1];
  if (n_in >= 2 && in_sizes[0] < in_sizes[1]){
    fr  = (const float*)d_in[1];
    tpl = (const float*)d_in[0];
  }
  float* out = (float*)d_out;
  k_cc<<<dim3(64, 32), 128>>>(fr, tpl);
  k_stats<<<dim3(33, 32), 512>>>(fr, tpl);
  k_shiftphase<<<32, 512>>>(fr);
  k_pass1<<<2048, 256>>>(fr);
  k_pass2<<<2048, 256>>>(out);
}

// round 7
// speedup vs baseline: 2.7214x; 1.0351x over previous
#include <cuda_runtime.h>
#include <math.h>

#define HH 512
#define WW 512
#define NB 32
#define NPIX (HH*WW)
#define EPSV 1e-8f
#define INV_A (1.0f/252004.0f)   // 1/(502*502)
#define STPITCH 656
#define SW(c) ((c) + 4*((c)>>4))
#define FNB 262144.0
#define SKF(i) ((i) + ((i) >> 3))
#define SZN 576

// ---------------- static device storage --------------------------------------
__device__ float  g_yr[NB*NPIX];       // 32 MB real intermediate [b][j][i]
__device__ float  g_p1[NB][32][WW];
__device__ float  g_p2[NB][32][WW];
__device__ float  g_p3[NB][32][WW];
__device__ double g_tq1[32], g_tq2[32];
__device__ float  g_ccp[NB][64][121];  // per-block cc partials (no atomics)
__device__ float  g_nx[NB], g_ny[NB], g_corr[NB];
__device__ float2 g_phx[NB][512];
__device__ float2 g_phy[NB][512];

// ---------------- complex helpers --------------------------------------------
__device__ __forceinline__ float2 cmulf(float2 a, float2 b){
  return make_float2(a.x*b.x - a.y*b.y, a.x*b.y + a.y*b.x);
}
__device__ __forceinline__ float2 caddf(float2 a, float2 b){ return make_float2(a.x+b.x, a.y+b.y); }
__device__ __forceinline__ float2 csubf(float2 a, float2 b){ return make_float2(a.x-b.x, a.y-b.y); }
__device__ __forceinline__ float2 mulnegi(float2 a){ return make_float2(a.y, -a.x); }

__device__ __forceinline__ void dft8(float2 a[8]){
  const float RT = 0.70710678118654752440f;
  float2 s0=caddf(a[0],a[4]), s1=caddf(a[1],a[5]), s2=caddf(a[2],a[6]), s3=caddf(a[3],a[7]);
  float2 d0=csubf(a[0],a[4]), d1=csubf(a[1],a[5]), d2=csubf(a[2],a[6]), d3=csubf(a[3],a[7]);
  d1 = cmulf(d1, make_float2( RT,-RT));
  d2 = mulnegi(d2);
  d3 = cmulf(d3, make_float2(-RT,-RT));
  float2 p0=caddf(s0,s2), p1=caddf(s1,s3), m0=csubf(s0,s2), m1=mulnegi(csubf(s1,s3));
  float2 q0=caddf(d0,d2), q1=caddf(d1,d3), n0=csubf(d0,d2), n1=mulnegi(csubf(d1,d3));
  a[0]=caddf(p0,p1); a[4]=csubf(p0,p1); a[2]=caddf(m0,m1); a[6]=csubf(m0,m1);
  a[1]=caddf(q0,q1); a[5]=csubf(q0,q1); a[3]=caddf(n0,n1); a[7]=csubf(n0,n1);
}

// ---------------- float2 smem FFT stages --------------------------------------
template<int L>
__device__ __forceinline__ void stage_load2(const float2* s, const float2* tw,
                                            float2 a[8], int t){
  #pragma unroll
  for (int r = 0; r < 8; r++) a[r] = s[SKF(t + 64*r)];
  if (L > 1){
    int jm = t % L;
    #pragma unroll
    for (int r = 1; r < 8; r++){
      float2 w = tw[(jm * r * (64/L)) & 511];
      a[r] = cmulf(a[r], w);
    }
  }
}

template<int L>
__device__ __forceinline__ void stage_store2(float2* s, const float2 a[8], int t){
  int jd = t / L, jm = t % L;
  #pragma unroll
  for (int r = 0; r < 8; r++) s[SKF(jd*8*L + jm + L*r)] = a[r];
}

// Full 512-pt forward FFT on registers (a[r] = x[t+64r] in, X[t+64r] out).
// Caller must guarantee smem idle at entry (a __syncthreads since last smem read).
__device__ __forceinline__ void fft512f2(float2 a[8], float2* s,
                                         const float2* stw, int t){
  dft8(a);
  stage_store2<1>(s, a, t);
  __syncthreads();
  stage_load2<8>(s, stw, a, t);
  dft8(a);
  __syncthreads();
  stage_store2<8>(s, a, t);
  __syncthreads();
  stage_load2<64>(s, stw, a, t);
  dft8(a);
}

// ---------------- stats: frame partial sums + template moments ----------------
__global__ void k_stats(const float* __restrict__ fr, const float* __restrict__ tpl){
  __shared__ double sd[512], sq[512];
  int b = blockIdx.x, ry = blockIdx.y;
  int j = threadIdx.x;
  if (b < NB){
    const float* xb = fr + (size_t)b*NPIX + (size_t)ry*16*WW;
    float s1 = 0.f, s2 = 0.f, s3 = 0.f;
    #pragma unroll
    for (int i = 0; i < 16; i++){
      float v = xb[(size_t)i*WW + j];
      s1 += v; s2 = fmaf(v, v, s2);
      s3 += (i & 1) ? -v : v;
    }
    g_p1[b][ry][j] = s1;
    g_p2[b][ry][j] = s2;
    g_p3[b][ry][j] = s3;
  } else {
    const float* tb = tpl + (size_t)ry*16*WW;
    double s = 0.0, q = 0.0;
    #pragma unroll
    for (int i = 0; i < 16; i++){
      float v = tb[(size_t)i*WW + j];
      s += (double)v; q += (double)v*(double)v;
    }
    sd[j] = s; sq[j] = q; __syncthreads();
    for (int o = 256; o; o >>= 1){
      if (j < o){ sd[j] += sd[j+o]; sq[j] += sq[j+o]; }
      __syncthreads();
    }
    if (j == 0){ g_tq1[ry] = sd[0]; g_tq2[ry] = sq[0]; }
  }
}

// ---------------- direct circular cross-correlation (121 shifts) --------------
__global__ void __launch_bounds__(128) k_cc(const float* __restrict__ fr,
                                            const float* __restrict__ tpl){
  __shared__ float st[18*STPITCH];     // 46.1 KB (reused as reduce scratch)
  int b  = blockIdx.y;
  int r0 = blockIdx.x * 8;
  int tid = threadIdx.x;               // 128
  for (int e = tid; e < 18*522; e += 128){
    int rr = e / 522, c = e - rr*522;
    int gi = (r0 - 5 + rr) & 511;
    int gj = (c - 5) & 511;
    st[rr*STPITCH + SW(c)] = tpl[gi*WW + gj] - 2.0f;
  }
  __syncthreads();
  int lane = tid & 31, warp = tid >> 5;
  int nd = (warp == 3) ? 2 : 3;
  int j0 = lane * 16;
  float acc[3][11];
  #pragma unroll
  for (int s = 0; s < 3; s++)
    #pragma unroll
    for (int d = 0; d < 11; d++) acc[s][d] = 0.f;
  const float* xbase = fr + ((size_t)b*512 + r0)*512 + j0;
  #pragma unroll 1
  for (int il = 0; il < 8; il++){
    float4 xq[4];
    #pragma unroll
    for (int k = 0; k < 4; k++)
      xq[k] = *reinterpret_cast<const float4*>(xbase + (size_t)il*512 + 4*k);
    float xv[16];
    #pragma unroll
    for (int k = 0; k < 4; k++){ xv[4*k]=xq[k].x; xv[4*k+1]=xq[k].y; xv[4*k+2]=xq[k].z; xv[4*k+3]=xq[k].w; }
    #pragma unroll
    for (int s = 0; s < 3; s++){
      if (s < nd){
        int dxi = warp + 4*s;
        int trow = il - dxi + 10;          // in [0,17]
        const float* base = st + trow*STPITCH + 20*lane;
        float4 tq[7];
        #pragma unroll
        for (int k = 0; k < 4; k++) tq[k] = *reinterpret_cast<const float4*>(base + 4*k);
        #pragma unroll
        for (int k = 0; k < 3; k++) tq[4+k] = *reinterpret_cast<const float4*>(base + 20 + 4*k);
        float tv[28];
        #pragma unroll
        for (int k = 0; k < 7; k++){
          int o = (k < 4) ? 4*k : 16 + 4*(k-4);
          tv[o]=tq[k].x; tv[o+1]=tq[k].y; tv[o+2]=tq[k].z; tv[o+3]=tq[k].w;
        }
        #pragma unroll
        for (int d = 0; d < 11; d++)
          #pragma unroll
          for (int u = 0; u < 16; u++)
            acc[s][d] = fmaf(xv[u], tv[u + 10 - d], acc[s][d]);
      }
    }
  }
  __syncthreads();
  float* red = st + warp * (32*37);
  #pragma unroll
  for (int k = 0; k < 33; k++)
    red[lane*37 + k] = acc[k/11][k - (k/11)*11];
  __syncwarp();
  #pragma unroll
  for (int rnd = 0; rnd < 2; rnd++){
    int L = lane + 32*rnd;
    if (L < nd*11){
      float s = 0.f;
      #pragma unroll
      for (int l = 0; l < 32; l++) s += red[l*37 + L];
      int dxi = warp + 4*(L/11);
      g_ccp[b][blockIdx.x][dxi*11 + (L - (L/11)*11)] = s;
    }
  }
}

// ---------------- bands + denom + cc-combine + argmax + parabola + phases -----
__global__ void __launch_bounds__(512) k_shiftphase(const float* __restrict__ fr){
  __shared__ float sb1[11][512];
  __shared__ float sb2[11][512];
  __shared__ float part1[242], part2[242];
  __shared__ float ncc[121];
  __shared__ float wp1[16], wp2[16];
  __shared__ float s_shx, s_shy, s_fm, s_T;
  __shared__ double s_tm, s_tvar;
  int b = blockIdx.x, t = threadIdx.x;
  if (t == 0){
    double S = 0.0, Q = 0.0;
    #pragma unroll
    for (int k = 0; k < 32; k++){ S += g_tq1[k]; Q += g_tq2[k]; }
    double tm = S / FNB;
    s_tm = tm;
    s_tvar = Q - FNB*tm*tm;
  }
  float s1 = 0.f, s2 = 0.f, s3 = 0.f;
  #pragma unroll
  for (int ry = 0; ry < 32; ry++){
    s1 += g_p1[b][ry][t]; s2 += g_p2[b][ry][t]; s3 += g_p3[b][ry][t];
  }
  const float* xb = fr + (size_t)b*NPIX;
  float topv[10], botv[10];
  #pragma unroll
  for (int i = 0; i < 10; i++) topv[i] = xb[(size_t)i*WW + t];
  #pragma unroll
  for (int i = 0; i < 10; i++) botv[i] = xb[(size_t)(502+i)*WW + t];
  float bs1[11], bs2[11];
  bs1[10] = 0.f; bs2[10] = 0.f;
  #pragma unroll
  for (int m = 9; m >= 0; m--){
    bs1[m] = bs1[m+1] + botv[m];
    bs2[m] = bs2[m+1] + botv[m]*botv[m];
  }
  float tp1 = 0.f, tp2 = 0.f;
  #pragma unroll
  for (int p = 0; p < 11; p++){
    sb1[p][t] = s1 - tp1 - bs1[p];
    sb2[p][t] = s2 - tp2 - bs2[p];
    if (p < 10){ tp1 += topv[p]; tp2 += topv[p]*topv[p]; }
  }
  float rsum = s1;
  float csum = (t & 1) ? -s3 : s3;
  #pragma unroll
  for (int o = 16; o; o >>= 1){
    rsum += __shfl_down_sync(0xffffffffu, rsum, o);
    csum += __shfl_down_sync(0xffffffffu, csum, o);
  }
  if ((t & 31) == 0){ wp1[t>>5] = rsum; wp2[t>>5] = csum; }
  __syncthreads();
  if (t == 0){
    float a = 0.f, c = 0.f;
    #pragma unroll
    for (int k = 0; k < 16; k++){ a += wp1[k]; c += wp2[k]; }
    s_fm = a / (float)NPIX;
    s_T = c;
  }
  if (t < 242){
    int w = t >> 1, s = t & 1;
    int p = w / 11, q = w - 11*p;
    int j0 = q + 251*s;
    float a = 0.f, c = 0.f;
    for (int j = j0; j < j0 + 251; j++){ a += sb1[p][j]; c += sb2[p][j]; }
    part1[t] = a; part2[t] = c;
  }
  __syncthreads();
  if (t < 121){
    float w1 = part1[2*t] + part1[2*t+1];
    float w2 = part2[2*t] + part2[2*t+1];
    float ls  = w1 * INV_A;
    float lsq = w2 * INV_A;
    float var = lsq - ls*ls*INV_A + EPSV;
    if (var < 0.f) var = 0.f;
    float den = sqrtf(((float)s_tvar + EPSV) * var);
    float ccs = 0.f;
    for (int k = 0; k < 64; k++) ccs += g_ccp[b][k][t];
    double corr = (double)s_fm * FNB * (s_tm - 2.0);
    float num = fabsf((float)((double)ccs - corr));
    float v = num / den;
    if (isnan(v)) v = 0.f;
    ncc[t] = v;
  }
  __syncthreads();
  if (t == 0){
    float best = -1e30f; int am = 0;
    for (int k = 0; k < 121; k++){ if (ncc[k] > best){ best = ncc[k]; am = k; } }
    int xi = am / 11, yi = am % 11;
    float shx = -(float)(xi - 5);
    float shy = -(float)(yi - 5);
    int xm = xi - 1; if (xm < 0) xm += 11;   // jnp negative index wraps
    int xp = xi + 1; if (xp > 10) xp = 10;   // jnp OOB gather clamps
    int ym = yi - 1; if (ym < 0) ym += 11;
    int yp = yi + 1; if (yp > 10) yp = 10;
    float l0  = logf(ncc[xi*11 + yi]);
    float lxm = logf(ncc[xm*11 + yi]);
    float lxp = logf(ncc[xp*11 + yi]);
    float lym = logf(ncc[xi*11 + ym]);
    float lyp = logf(ncc[xi*11 + yp]);
    shx -= (lxm - lxp) / (2.f*lxm - 4.f*l0 + 2.f*lxp);
    shy -= (lym - lyp) / (2.f*lym - 4.f*l0 + 2.f*lyp);
    s_shx = shx; s_shy = shy;
    float nx = sinpif(shx), ny = sinpif(shy);
    g_nx[b] = nx; g_ny[b] = ny;
    g_corr[b] = nx * ny * s_T * (1.f/262144.f);
  }
  __syncthreads();
  float nr = (t < 256) ? (float)t : (float)(t - 512);
  float2 py, px;
  sincospif(-s_shy * nr * (1.f/256.f), &py.y, &py.x);
  sincospif(-s_shx * nr * (1.f/256.f), &px.y, &px.x);
  g_phy[b][t] = py;
  g_phx[b][t] = px;
}

// ---------------- pass 1: 2 packed real rows per FFT, real transposed output --
__global__ void __launch_bounds__(256) k_pass1(const float* __restrict__ fr){
  __shared__ float2 sz[4][SZN];
  __shared__ float2 stw[512];
  __shared__ float2 sv[4];
  int tid = threadIdx.x;
  int g   = tid >> 6;
  int t   = tid & 63;
  int bi  = blockIdx.x;            // 0..2047
  int b   = bi >> 6;
  int i0  = (bi & 63) * 8;
  const float* p1 = fr + ((size_t)b*512 + i0 + 2*g) * 512;
  const float* p2 = p1 + 512;
  const float2* ph = &g_phy[b][0];
  float ny = g_ny[b];
  float sg = (t & 1) ? -1.f : 1.f;

  for (int i = tid; i < 512; i += 256){
    float2 w;
    sincospif(-(float)i * (1.f/256.f), &w.y, &w.x);
    stw[i] = w;
  }

  float2* s = sz[g];
  float2 a[8];
  #pragma unroll
  for (int r = 0; r < 8; r++) a[r] = make_float2(p1[t + 64*r], p2[t + 64*r]);
  __syncthreads();   // stw ready
  fft512f2(a, s, stw, t);                // V = F(x1 + i x2)
  if (t == 0) sv[g] = a[4];              // V[256]
  __syncthreads();                       // sv ready; smem reads of fft done
  float2 V256 = sv[g];
  float b1 = ny * V256.x * (1.f/512.f);
  float b2 = ny * V256.y * (1.f/512.f);
  #pragma unroll
  for (int r = 0; r < 8; r++){
    float2 p = ph[t + 64*r];
    float xr = a[r].x*p.x - a[r].y*p.y;
    float xi = a[r].x*p.y + a[r].y*p.x;
    a[r] = make_float2(xr * (1.f/512.f), -xi * (1.f/512.f));
  }
  fft512f2(a, s, stw, t);                // u = conj(result)
  __syncthreads();                       // all smem reads done before overwrite
  // stage (y1, y2) = unpacked rows, plain indexing (conflict-free)
  #pragma unroll
  for (int r = 0; r < 8; r++){
    int j = t + 64*r;
    s[j] = make_float2(a[r].x + sg*b2, -a[r].y - sg*b1);
  }
  __syncthreads();
  for (int idx = tid; idx < 512; idx += 256){
    float2 v0 = sz[0][idx], v1 = sz[1][idx], v2 = sz[2][idx], v3 = sz[3][idx];
    float4 w1 = make_float4(v0.x, v0.y, v1.x, v1.y);
    float4 w2 = make_float4(v2.x, v2.y, v3.x, v3.y);
    float4* op = reinterpret_cast<float4*>(g_yr + ((size_t)b*512 + idx)*512 + i0);
    op[0] = w1; op[1] = w2;
  }
}

// ---------------- pass 2: 2 packed real columns per FFT, final output ---------
__global__ void __launch_bounds__(256) k_pass2(float* __restrict__ out){
  __shared__ float2 sz[4][SZN];
  __shared__ float2 stw[512];
  __shared__ float2 sv[4];
  int tid = threadIdx.x;
  int g   = tid >> 6;
  int t   = tid & 63;
  int bi  = blockIdx.x;
  int b   = bi >> 6;
  int j1  = (bi & 63) * 8 + 2*g;
  const float* c1 = g_yr + ((size_t)b*512 + j1) * 512;
  const float* c2 = c1 + 512;
  const float2* ph = &g_phx[b][0];
  float nx = g_nx[b];
  float corr = g_corr[b];
  float sg = (t & 1) ? -1.f : 1.f;

  for (int i = tid; i < 512; i += 256){
    float2 w;
    sincospif(-(float)i * (1.f/256.f), &w.y, &w.x);
    stw[i] = w;
  }

  float2* s = sz[g];
  float2 a[8];
  #pragma unroll
  for (int r = 0; r < 8; r++) a[r] = make_float2(c1[t + 64*r], c2[t + 64*r]);
  __syncthreads();   // stw ready
  fft512f2(a, s, stw, t);                // U = F(z1 + i z2)
  if (t == 0) sv[g] = a[4];
  __syncthreads();
  float2 U256 = sv[g];
  float e1 = nx * U256.x * (1.f/512.f) - corr;
  float e2 = nx * U256.y * (1.f/512.f) - corr;
  #pragma unroll
  for (int r = 0; r < 8; r++){
    float2 p = ph[t + 64*r];
    float xr = a[r].x*p.x - a[r].y*p.y;
    float xi = a[r].x*p.y + a[r].y*p.x;
    a[r] = make_float2(xr * (1.f/512.f), -xi * (1.f/512.f));
  }
  fft512f2(a, s, stw, t);
  float* r1 = out + ((size_t)b*512 + j1) * 512;
  float* r2 = r1 + 512;
  #pragma unroll
  for (int r = 0; r < 8; r++){
    int i = t + 64*r;
    r1[i] = a[r].x + sg*e2;
    r2[i] = -a[r].y - sg*e1;
  }
}

// ---------------- launcher -----------------------------------------------------
extern "C" void kernel_launch(void* const* d_in, const int* in_sizes, int n_in,
                              void* d_out, int out_size){
  const float* fr  = (const float*)d_in[0];
  const float* tpl = (const float*)d_in[1];
  if (n_in >= 2 && in_sizes[0] < in_sizes[1]){
    fr  = (const float*)d_in[1];
    tpl = (const float*)d_in[0];
  }
  float* out = (float*)d_out;
  k_cc<<<dim3(64, 32), 128>>>(fr, tpl);
  k_stats<<<dim3(33, 32), 512>>>(fr, tpl);
  k_shiftphase<<<32, 512>>>(fr);
  k_pass1<<<2048, 256>>>(fr);
  k_pass2<<<2048, 256>>>(out);
}